// round 1
// baseline (speedup 1.0000x reference)
#include <cuda_runtime.h>
#include <cuda_bf16.h>
#include <math.h>

// Problem constants
#define BATCH 4
#define SEQ   2048
#define EMBD  1024
#define NHEAD 16
#define HDIM  64
#define MTOT  (BATCH*SEQ)   // 8192

// Scratch (device globals: allocation-free rule)
__device__ float g_q[BATCH*NHEAD*SEQ*HDIM];  // [B,H,T,d]
__device__ float g_k[BATCH*NHEAD*SEQ*HDIM];
__device__ float g_v[BATCH*NHEAD*SEQ*HDIM];
__device__ float g_y[BATCH*SEQ*EMBD];        // [B,T,C] attention output

// ---------------------------------------------------------------------------
// GEMM: out = x @ W, 128x128 block tile, BK=16, 256 threads, 8x8 micro-tile.
// gridDim.z in {0,1,2} selects Wq/Wk/Wv and writes to [B,H,T,d] layout.
// ---------------------------------------------------------------------------
__global__ __launch_bounds__(256) void gemm_qkv(
    const float* __restrict__ x,
    const float* __restrict__ Wq,
    const float* __restrict__ Wk,
    const float* __restrict__ Wv)
{
    const float* W   = (blockIdx.z == 0) ? Wq : (blockIdx.z == 1) ? Wk : Wv;
    float*       out = (blockIdx.z == 0) ? g_q : (blockIdx.z == 1) ? g_k : g_v;

    __shared__ float As[16][128];
    __shared__ float Bs[16][128];

    const int tid = threadIdx.x;
    const int m0 = blockIdx.y * 128;
    const int n0 = blockIdx.x * 128;
    const int tm = (tid >> 4) << 3;   // (tid/16)*8
    const int tn = (tid & 15) << 3;   // (tid%16)*8

    float acc[8][8];
#pragma unroll
    for (int i = 0; i < 8; i++)
#pragma unroll
        for (int j = 0; j < 8; j++) acc[i][j] = 0.f;

    for (int k0 = 0; k0 < EMBD; k0 += 16) {
        // load A tile (128x16) transposed into As[k][m]
#pragma unroll
        for (int it = 0; it < 2; it++) {
            int r = (tid >> 2) + it * 64;     // row in tile
            int c = (tid & 3) << 2;           // col in BK
            float4 a = *(const float4*)&x[(size_t)(m0 + r) * EMBD + k0 + c];
            As[c + 0][r] = a.x; As[c + 1][r] = a.y;
            As[c + 2][r] = a.z; As[c + 3][r] = a.w;
        }
        // load B tile (16x128) direct
#pragma unroll
        for (int it = 0; it < 2; it++) {
            int r = (tid >> 5) + it * 8;
            int c = (tid & 31) << 2;
            *(float4*)&Bs[r][c] = *(const float4*)&W[(size_t)(k0 + r) * EMBD + n0 + c];
        }
        __syncthreads();

#pragma unroll
        for (int k = 0; k < 16; k++) {
            float af[8], bf[8];
            *(float4*)&af[0] = *(float4*)&As[k][tm];
            *(float4*)&af[4] = *(float4*)&As[k][tm + 4];
            *(float4*)&bf[0] = *(float4*)&Bs[k][tn];
            *(float4*)&bf[4] = *(float4*)&Bs[k][tn + 4];
#pragma unroll
            for (int i = 0; i < 8; i++)
#pragma unroll
                for (int j = 0; j < 8; j++)
                    acc[i][j] = fmaf(af[i], bf[j], acc[i][j]);
        }
        __syncthreads();
    }

    // epilogue: out[((b*H+h)*T + t)*d + dd]
#pragma unroll
    for (int i = 0; i < 8; i++) {
        int m = m0 + tm + i;
        int b = m >> 11;          // /2048
        int t = m & 2047;
#pragma unroll
        for (int jj = 0; jj < 8; jj += 4) {
            int n  = n0 + tn + jj;
            int h  = n >> 6;
            int dd = n & 63;
            float4 v = make_float4(acc[i][jj], acc[i][jj+1], acc[i][jj+2], acc[i][jj+3]);
            *(float4*)&out[(((size_t)(b * NHEAD + h)) * SEQ + t) * HDIM + dd] = v;
        }
    }
}

// ---------------------------------------------------------------------------
// Output projection: d_out = g_y @ Wp + bp
// ---------------------------------------------------------------------------
__global__ __launch_bounds__(256) void gemm_out(
    const float* __restrict__ Wp,
    const float* __restrict__ bp,
    float* __restrict__ out)
{
    __shared__ float As[16][128];
    __shared__ float Bs[16][128];

    const int tid = threadIdx.x;
    const int m0 = blockIdx.y * 128;
    const int n0 = blockIdx.x * 128;
    const int tm = (tid >> 4) << 3;
    const int tn = (tid & 15) << 3;

    float acc[8][8];
#pragma unroll
    for (int i = 0; i < 8; i++)
#pragma unroll
        for (int j = 0; j < 8; j++) acc[i][j] = 0.f;

    for (int k0 = 0; k0 < EMBD; k0 += 16) {
#pragma unroll
        for (int it = 0; it < 2; it++) {
            int r = (tid >> 2) + it * 64;
            int c = (tid & 3) << 2;
            float4 a = *(const float4*)&g_y[(size_t)(m0 + r) * EMBD + k0 + c];
            As[c + 0][r] = a.x; As[c + 1][r] = a.y;
            As[c + 2][r] = a.z; As[c + 3][r] = a.w;
        }
#pragma unroll
        for (int it = 0; it < 2; it++) {
            int r = (tid >> 5) + it * 8;
            int c = (tid & 31) << 2;
            *(float4*)&Bs[r][c] = *(const float4*)&Wp[(size_t)(k0 + r) * EMBD + n0 + c];
        }
        __syncthreads();

#pragma unroll
        for (int k = 0; k < 16; k++) {
            float af[8], bf[8];
            *(float4*)&af[0] = *(float4*)&As[k][tm];
            *(float4*)&af[4] = *(float4*)&As[k][tm + 4];
            *(float4*)&bf[0] = *(float4*)&Bs[k][tn];
            *(float4*)&bf[4] = *(float4*)&Bs[k][tn + 4];
#pragma unroll
            for (int i = 0; i < 8; i++)
#pragma unroll
                for (int j = 0; j < 8; j++)
                    acc[i][j] = fmaf(af[i], bf[j], acc[i][j]);
        }
        __syncthreads();
    }

    float bias[8];
#pragma unroll
    for (int j = 0; j < 8; j++) bias[j] = __ldg(&bp[n0 + tn + j]);

#pragma unroll
    for (int i = 0; i < 8; i++) {
        int m = m0 + tm + i;
#pragma unroll
        for (int jj = 0; jj < 8; jj += 4) {
            float4 v = make_float4(acc[i][jj] + bias[jj],
                                   acc[i][jj+1] + bias[jj+1],
                                   acc[i][jj+2] + bias[jj+2],
                                   acc[i][jj+3] + bias[jj+3]);
            *(float4*)&out[(size_t)m * EMBD + n0 + tn + jj] = v;
        }
    }
}

// ---------------------------------------------------------------------------
// Causal flash attention, fp32. Br=Bc=64, d=64, 256 threads (16x16),
// each thread owns a 4x4 tile of S / O.
// Dynamic smem: Qs, Ks, Vs, Ps each 64 x 68 floats.
// ---------------------------------------------------------------------------
#define PAD 68

__global__ __launch_bounds__(256) void attn_fwd()
{
    extern __shared__ float sm[];
    float* Qs = sm;
    float* Ks = sm + 64 * PAD;
    float* Vs = sm + 2 * 64 * PAD;
    float* Ps = sm + 3 * 64 * PAD;

    const int tid = threadIdx.x;
    const int ty = tid >> 4;      // 0..15
    const int tx = tid & 15;      // 0..15

    const int qt = blockIdx.x;    // query tile
    const int h  = blockIdx.y;
    const int b  = blockIdx.z;
    const int q0 = qt * 64;

    const size_t head_base = ((size_t)(b * NHEAD + h)) * SEQ * HDIM;
    const float* gq = g_q + head_base + (size_t)q0 * HDIM;
    const float* gk = g_k + head_base;
    const float* gv = g_v + head_base;

    // load Q tile (scaled by 1/sqrt(d) = 0.125)
#pragma unroll
    for (int it = 0; it < 4; it++) {
        int e = tid + it * 256;           // float4 index, 0..1023
        int r = e >> 4;
        int c = (e & 15) << 2;
        float4 v = *(const float4*)&gq[(size_t)r * HDIM + c];
        v.x *= 0.125f; v.y *= 0.125f; v.z *= 0.125f; v.w *= 0.125f;
        *(float4*)&Qs[r * PAD + c] = v;
    }

    float m_i[4], l_i[4], acc[4][4];
#pragma unroll
    for (int i = 0; i < 4; i++) {
        m_i[i] = -INFINITY; l_i[i] = 0.f;
#pragma unroll
        for (int j = 0; j < 4; j++) acc[i][j] = 0.f;
    }
    __syncthreads();  // Qs visible (also first K/V load below syncs again)

    for (int kt = 0; kt <= qt; kt++) {
        const int k0 = kt * 64;
        // load K,V tiles
#pragma unroll
        for (int it = 0; it < 4; it++) {
            int e = tid + it * 256;
            int r = e >> 4;
            int c = (e & 15) << 2;
            *(float4*)&Ks[r * PAD + c] = *(const float4*)&gk[(size_t)(k0 + r) * HDIM + c];
            *(float4*)&Vs[r * PAD + c] = *(const float4*)&gv[(size_t)(k0 + r) * HDIM + c];
        }
        __syncthreads();

        // S = Q K^T (4x4 per thread)
        float s[4][4];
#pragma unroll
        for (int i = 0; i < 4; i++)
#pragma unroll
            for (int j = 0; j < 4; j++) s[i][j] = 0.f;

#pragma unroll
        for (int k = 0; k < 64; k += 4) {
            float4 q[4], kk[4];
#pragma unroll
            for (int i = 0; i < 4; i++) q[i]  = *(float4*)&Qs[(ty * 4 + i) * PAD + k];
#pragma unroll
            for (int j = 0; j < 4; j++) kk[j] = *(float4*)&Ks[(tx * 4 + j) * PAD + k];
#pragma unroll
            for (int i = 0; i < 4; i++)
#pragma unroll
                for (int j = 0; j < 4; j++) {
                    s[i][j] = fmaf(q[i].x, kk[j].x, s[i][j]);
                    s[i][j] = fmaf(q[i].y, kk[j].y, s[i][j]);
                    s[i][j] = fmaf(q[i].z, kk[j].z, s[i][j]);
                    s[i][j] = fmaf(q[i].w, kk[j].w, s[i][j]);
                }
        }

        // causal mask: only the diagonal tile needs it
        if (kt == qt) {
#pragma unroll
            for (int i = 0; i < 4; i++)
#pragma unroll
                for (int j = 0; j < 4; j++)
                    if (tx * 4 + j > ty * 4 + i) s[i][j] = -INFINITY;
        }

        // online softmax update (row groups = 16 contiguous lanes)
#pragma unroll
        for (int i = 0; i < 4; i++) {
            float mloc = fmaxf(fmaxf(s[i][0], s[i][1]), fmaxf(s[i][2], s[i][3]));
#pragma unroll
            for (int o = 1; o < 16; o <<= 1)
                mloc = fmaxf(mloc, __shfl_xor_sync(0xffffffffu, mloc, o));
            float mn = fmaxf(m_i[i], mloc);
            float fac = expf(m_i[i] - mn);
            float psum = 0.f;
#pragma unroll
            for (int j = 0; j < 4; j++) {
                float p = expf(s[i][j] - mn);
                s[i][j] = p;
                psum += p;
            }
#pragma unroll
            for (int o = 1; o < 16; o <<= 1)
                psum += __shfl_xor_sync(0xffffffffu, psum, o);
            l_i[i] = l_i[i] * fac + psum;
            m_i[i] = mn;
#pragma unroll
            for (int j = 0; j < 4; j++) acc[i][j] *= fac;
        }

        // stage P to smem
#pragma unroll
        for (int i = 0; i < 4; i++)
#pragma unroll
            for (int j = 0; j < 4; j++)
                Ps[(ty * 4 + i) * PAD + tx * 4 + j] = s[i][j];
        __syncthreads();

        // O += P @ V
#pragma unroll
        for (int k = 0; k < 64; k++) {
            float4 vv = *(float4*)&Vs[k * PAD + tx * 4];
#pragma unroll
            for (int i = 0; i < 4; i++) {
                float p = Ps[(ty * 4 + i) * PAD + k];
                acc[i][0] = fmaf(p, vv.x, acc[i][0]);
                acc[i][1] = fmaf(p, vv.y, acc[i][1]);
                acc[i][2] = fmaf(p, vv.z, acc[i][2]);
                acc[i][3] = fmaf(p, vv.w, acc[i][3]);
            }
        }
        __syncthreads();  // protect Ks/Vs/Ps before next iteration
    }

    // write O/l to g_y in [B,T,C] layout, c = h*64 + col
#pragma unroll
    for (int i = 0; i < 4; i++) {
        float rn = 1.0f / l_i[i];
        int t = q0 + ty * 4 + i;
        float4 v = make_float4(acc[i][0] * rn, acc[i][1] * rn,
                               acc[i][2] * rn, acc[i][3] * rn);
        *(float4*)&g_y[((size_t)b * SEQ + t) * EMBD + h * HDIM + tx * 4] = v;
    }
}

// ---------------------------------------------------------------------------
extern "C" void kernel_launch(void* const* d_in, const int* in_sizes, int n_in,
                              void* d_out, int out_size)
{
    const float* x  = (const float*)d_in[0];
    const float* Wq = (const float*)d_in[1];
    const float* Wk = (const float*)d_in[2];
    const float* Wv = (const float*)d_in[3];
    const float* Wp = (const float*)d_in[4];
    const float* bp = (const float*)d_in[5];
    float* out = (float*)d_out;

    // QKV projections: grid (N/128, M/128, 3)
    gemm_qkv<<<dim3(EMBD / 128, MTOT / 128, 3), 256>>>(x, Wq, Wk, Wv);

    // attention
    const int attn_smem = 4 * 64 * PAD * sizeof(float);  // 69632 B
    static bool attr_set = false;
    if (!attr_set) {
        cudaFuncSetAttribute(attn_fwd, cudaFuncAttributeMaxDynamicSharedMemorySize, attn_smem);
        attr_set = true;
    }
    attn_fwd<<<dim3(SEQ / 64, NHEAD, BATCH), 256, attn_smem>>>();

    // output projection + bias
    gemm_out<<<dim3(EMBD / 128, MTOT / 128), 256>>>(Wp, bp, out);
}

// round 3
// speedup vs baseline: 1.3535x; 1.3535x over previous
#include <cuda_runtime.h>
#include <cuda_bf16.h>
#include <math.h>
#include <stdint.h>

// Problem constants
#define BATCH 4
#define SEQ   2048
#define EMBD  1024
#define NHEAD 16
#define HDIM  64
#define MTOT  (BATCH*SEQ)   // 8192

// ---------------------------------------------------------------------------
// Device scratch (allocation-free rule: __device__ globals)
// ---------------------------------------------------------------------------
__device__ float g_q[BATCH*NHEAD*SEQ*HDIM];   // [B,H,T,d]
__device__ float g_k[BATCH*NHEAD*SEQ*HDIM];
__device__ float g_v[BATCH*NHEAD*SEQ*HDIM];
__device__ float g_y[BATCH*SEQ*EMBD];         // attention output [B,T,C]

__device__ __nv_bfloat16 g_xhi[MTOT*EMBD];    // bf16 splits of x
__device__ __nv_bfloat16 g_xlo[MTOT*EMBD];
__device__ __nv_bfloat16 g_yhi[MTOT*EMBD];    // bf16 splits of y
__device__ __nv_bfloat16 g_ylo[MTOT*EMBD];
__device__ __nv_bfloat16 g_wthi[4*EMBD*EMBD]; // W^T hi: [z][n][k], z=q,k,v,p
__device__ __nv_bfloat16 g_wtlo[4*EMBD*EMBD];

// ---------------------------------------------------------------------------
// PTX helpers (arch-generic only: no tcgen05 — harness compiles compute_103)
// ---------------------------------------------------------------------------
__device__ __forceinline__ uint32_t smem_u32(const void* p) {
    uint32_t a;
    asm("{ .reg .u64 t; cvta.to.shared.u64 t, %1; cvt.u32.u64 %0, t; }"
        : "=r"(a) : "l"(p));
    return a;
}
__device__ __forceinline__ void cp16(uint32_t dst, const void* src) {
    asm volatile("cp.async.cg.shared.global [%0], [%1], 16;"
                 :: "r"(dst), "l"(src) : "memory");
}
#define CP_COMMIT() asm volatile("cp.async.commit_group;" ::: "memory")
#define CP_WAIT(n)  asm volatile("cp.async.wait_group %0;" :: "n"(n) : "memory")

#define LDSM_X4(r0, r1, r2, r3, addr) \
    asm volatile("ldmatrix.sync.aligned.m8n8.x4.shared.b16 {%0,%1,%2,%3}, [%4];" \
        : "=r"(r0), "=r"(r1), "=r"(r2), "=r"(r3) : "r"(addr))
#define LDSM_X2(r0, r1, addr) \
    asm volatile("ldmatrix.sync.aligned.m8n8.x2.shared.b16 {%0,%1}, [%2];" \
        : "=r"(r0), "=r"(r1) : "r"(addr))

#define MMA_BF16(d, a0, a1, a2, a3, b0, b1) \
    asm volatile("mma.sync.aligned.m16n8k16.row.col.f32.bf16.bf16.f32 " \
        "{%0,%1,%2,%3}, {%4,%5,%6,%7}, {%8,%9}, {%0,%1,%2,%3};" \
        : "+f"((d)[0]), "+f"((d)[1]), "+f"((d)[2]), "+f"((d)[3]) \
        : "r"(a0), "r"(a1), "r"(a2), "r"(a3), "r"(b0), "r"(b1))

__device__ __forceinline__ float ex2f(float x) {
    float y;
    asm("ex2.approx.f32 %0, %1;" : "=f"(y) : "f"(x));
    return y;
}

// ---------------------------------------------------------------------------
// Split fp32 -> bf16 hi + bf16 lo
// ---------------------------------------------------------------------------
__device__ __forceinline__ void split_bf16_val(float x, __nv_bfloat16& h, __nv_bfloat16& l) {
    h = __float2bfloat16_rn(x);
    l = __float2bfloat16_rn(x - __bfloat162float(h));
}

__global__ __launch_bounds__(256) void split_kernel(
    const float* __restrict__ in,
    __nv_bfloat16* __restrict__ hi, __nv_bfloat16* __restrict__ lo, int n4)
{
    int stride = gridDim.x * blockDim.x;
    for (int i = blockIdx.x * blockDim.x + threadIdx.x; i < n4; i += stride) {
        float4 v = ((const float4*)in)[i];
        __nv_bfloat16 h0, h1, h2, h3, l0, l1, l2, l3;
        split_bf16_val(v.x, h0, l0);
        split_bf16_val(v.y, h1, l1);
        split_bf16_val(v.z, h2, l2);
        split_bf16_val(v.w, h3, l3);
        __nv_bfloat162* hp = (__nv_bfloat162*)(hi + i * 4);
        __nv_bfloat162* lp = (__nv_bfloat162*)(lo + i * 4);
        hp[0] = __nv_bfloat162{h0, h1}; hp[1] = __nv_bfloat162{h2, h3};
        lp[0] = __nv_bfloat162{l0, l1}; lp[1] = __nv_bfloat162{l2, l3};
    }
}

// ---------------------------------------------------------------------------
// Weight transpose + split: Wt[z][n][k] = split(W[k][n])
// ---------------------------------------------------------------------------
__global__ __launch_bounds__(256) void wsplit_kernel(
    const float* __restrict__ Wq, const float* __restrict__ Wk,
    const float* __restrict__ Wv, const float* __restrict__ Wp)
{
    __shared__ float ts[32][33];
    const int z = blockIdx.z;
    const float* W = (z == 0) ? Wq : (z == 1) ? Wk : (z == 2) ? Wv : Wp;
    __nv_bfloat16* oh = g_wthi + (size_t)z * EMBD * EMBD;
    __nv_bfloat16* ol = g_wtlo + (size_t)z * EMBD * EMBD;
    const int k0 = blockIdx.x * 32;
    const int n0 = blockIdx.y * 32;
    const int tx = threadIdx.x & 31;
    const int ty = threadIdx.x >> 5;
#pragma unroll
    for (int i = 0; i < 4; i++) {
        int r = ty + i * 8;
        ts[r][tx] = W[(size_t)(k0 + r) * EMBD + n0 + tx];
    }
    __syncthreads();
#pragma unroll
    for (int i = 0; i < 4; i++) {
        int r = ty + i * 8;                 // n offset
        float v = ts[tx][r];                // W[k0+tx][n0+r]
        __nv_bfloat16 h, l;
        split_bf16_val(v, h, l);
        oh[(size_t)(n0 + r) * EMBD + k0 + tx] = h;
        ol[(size_t)(n0 + r) * EMBD + k0 + tx] = l;
    }
}

// ---------------------------------------------------------------------------
// bf16 mma.sync GEMM (split-bf16, 3 products): C = A @ B^T
// A: [M][K] bf16 hi/lo, B: [N][K] bf16 hi/lo (K contiguous both sides).
// Tile 128x128x32, 256 threads (8 warps, 2x4), 3-stage cp.async pipeline.
// mode 0: out -> g_q/g_k/g_v ([B,H,T,d]) by blockIdx.z;  mode 1: outp + bias.
// ---------------------------------------------------------------------------
#define BM 128
#define BN 128
#define BK 32
#define NCHUNK (EMBD / BK)    // 32
#define ROWB  80              // padded smem row: 32 bf16 (64B) + 16B pad
#define SA_HI 0
#define SA_LO 10240
#define SB_HI 20480
#define SB_LO 30720
#define STG   40960
#define GEMM_SMEM (3 * STG)   // 122880

__device__ __forceinline__ void load_stage(
    uint32_t stage_base,
    const __nv_bfloat16* __restrict__ Ahi, const __nv_bfloat16* __restrict__ Alo,
    const __nv_bfloat16* __restrict__ Bhi, const __nv_bfloat16* __restrict__ Blo,
    int m0, int n0, int kc, int tid)
{
#pragma unroll
    for (int i = 0; i < 2; i++) {
        int idx = tid + i * 256;          // 0..511 -> 128 rows x 4 chunks
        int r  = idx >> 2;
        int ch = idx & 3;
        uint32_t d = stage_base + (uint32_t)(r * ROWB + ch * 16);
        size_t ga = (size_t)(m0 + r) * EMBD + kc + ch * 8;
        size_t gb = (size_t)(n0 + r) * EMBD + kc + ch * 8;
        cp16(d + SA_HI, Ahi + ga);
        cp16(d + SA_LO, Alo + ga);
        cp16(d + SB_HI, Bhi + gb);
        cp16(d + SB_LO, Blo + gb);
    }
    CP_COMMIT();
}

__global__ __launch_bounds__(256, 1) void gemm_mma(
    const __nv_bfloat16* __restrict__ Ahi, const __nv_bfloat16* __restrict__ Alo,
    const __nv_bfloat16* __restrict__ Bhi_all, const __nv_bfloat16* __restrict__ Blo_all,
    const float* __restrict__ bias, float* __restrict__ outp, int mode)
{
    extern __shared__ char smch[];
    const uint32_t sb = smem_u32(smch);

    const int tid  = threadIdx.x;
    const int lane = tid & 31;
    const int wid  = tid >> 5;
    const int m_w  = (wid & 1) * 64;
    const int n_w  = (wid >> 1) * 32;
    const int n0 = blockIdx.x * BN;
    const int m0 = blockIdx.y * BM;
    const int z  = blockIdx.z;
    const __nv_bfloat16* Bhi = Bhi_all + (size_t)z * EMBD * EMBD;
    const __nv_bfloat16* Blo = Blo_all + (size_t)z * EMBD * EMBD;

    float acc[4][4][4];
#pragma unroll
    for (int i = 0; i < 4; i++)
#pragma unroll
        for (int j = 0; j < 4; j++)
#pragma unroll
            for (int e = 0; e < 4; e++) acc[i][j][e] = 0.f;

    // prologue: 3 stages in flight
    load_stage(sb + 0 * STG, Ahi, Alo, Bhi, Blo, m0, n0, 0 * BK, tid);
    load_stage(sb + 1 * STG, Ahi, Alo, Bhi, Blo, m0, n0, 1 * BK, tid);
    load_stage(sb + 2 * STG, Ahi, Alo, Bhi, Blo, m0, n0, 2 * BK, tid);

    // per-thread ldmatrix address components
    const uint32_t a_row_off = (uint32_t)((m_w + (lane & 15)) * ROWB) + ((lane >> 4) * 16);
    const uint32_t b_row_off = (uint32_t)((n_w + (lane & 7)) * ROWB) + (((lane >> 3) & 1) * 16);

    for (int c = 0; c < NCHUNK; c++) {
        const int s = c % 3;
        if (c >= NCHUNK - 3) CP_WAIT(0); else CP_WAIT(2);
        __syncthreads();

        const uint32_t stb = sb + (uint32_t)s * STG;
#pragma unroll
        for (int ks = 0; ks < 2; ks++) {
            uint32_t ahi[4][4], alo[4][4], bhi[4][2], blo[4][2];
            const uint32_t kso = (uint32_t)(ks * 32);   // 2 chunks of 16B
#pragma unroll
            for (int i = 0; i < 4; i++) {
                uint32_t aaddr = stb + a_row_off + (uint32_t)(i * 16 * ROWB) + kso;
                LDSM_X4(ahi[i][0], ahi[i][1], ahi[i][2], ahi[i][3], aaddr + SA_HI);
                LDSM_X4(alo[i][0], alo[i][1], alo[i][2], alo[i][3], aaddr + SA_LO);
            }
#pragma unroll
            for (int j = 0; j < 4; j++) {
                uint32_t baddr = stb + b_row_off + (uint32_t)(j * 8 * ROWB) + kso;
                LDSM_X2(bhi[j][0], bhi[j][1], baddr + SB_HI);
                LDSM_X2(blo[j][0], blo[j][1], baddr + SB_LO);
            }
#pragma unroll
            for (int i = 0; i < 4; i++)
#pragma unroll
                for (int j = 0; j < 4; j++) {
                    MMA_BF16(acc[i][j], ahi[i][0], ahi[i][1], ahi[i][2], ahi[i][3],
                             bhi[j][0], bhi[j][1]);
                    MMA_BF16(acc[i][j], ahi[i][0], ahi[i][1], ahi[i][2], ahi[i][3],
                             blo[j][0], blo[j][1]);
                    MMA_BF16(acc[i][j], alo[i][0], alo[i][1], alo[i][2], alo[i][3],
                             bhi[j][0], bhi[j][1]);
                }
        }
        __syncthreads();
        if (c + 3 < NCHUNK)
            load_stage(stb, Ahi, Alo, Bhi, Blo, m0, n0, (c + 3) * BK, tid);
    }

    // epilogue: D frag (c0,c1)@(row, col), (c2,c3)@(row+8, col); col=2*(lane&3)
    const int b  = m0 >> 11;                 // tile never crosses batch
    const int rr = m0 + m_w + (lane >> 2);
#pragma unroll
    for (int i = 0; i < 4; i++) {
        const int r0 = rr + i * 16;
        const int t0 = r0 & 2047;
#pragma unroll
        for (int j = 0; j < 4; j++) {
            const int cc = n0 + n_w + j * 8 + 2 * (lane & 3);
            if (mode == 0) {
                float* op = (z == 0) ? g_q : (z == 1) ? g_k : g_v;
                const int h  = cc >> 6;
                const int dd = cc & 63;
                float* p = op + (((size_t)(b * NHEAD + h) * SEQ + t0) << 6) + dd;
                *(float2*)p        = make_float2(acc[i][j][0], acc[i][j][1]);
                *(float2*)(p + (8 << 6)) = make_float2(acc[i][j][2], acc[i][j][3]);
            } else {
                float2 bv = *(const float2*)&bias[cc];
                float* p = outp + (size_t)r0 * EMBD + cc;
                *(float2*)p = make_float2(acc[i][j][0] + bv.x, acc[i][j][1] + bv.y);
                *(float2*)(p + 8 * EMBD) =
                    make_float2(acc[i][j][2] + bv.x, acc[i][j][3] + bv.y);
            }
        }
    }
}

// ---------------------------------------------------------------------------
// Causal flash attention, fp32 math + fast ex2 softmax (base-2 domain).
// Q pre-scaled by (1/sqrt(d)) * log2(e).
// ---------------------------------------------------------------------------
#define PAD 68
#define QSCALE 0.1803368801111137f   // 0.125 * log2(e)

__global__ __launch_bounds__(256, 2) void attn_fwd()
{
    extern __shared__ float sm[];
    float* Qs = sm;
    float* Ks = sm + 64 * PAD;
    float* Vs = sm + 2 * 64 * PAD;
    float* Ps = sm + 3 * 64 * PAD;

    const int tid = threadIdx.x;
    const int ty = tid >> 4;
    const int tx = tid & 15;

    const int qt = blockIdx.x;
    const int h  = blockIdx.y;
    const int b  = blockIdx.z;
    const int q0 = qt * 64;

    const size_t head_base = ((size_t)(b * NHEAD + h)) * SEQ * HDIM;
    const float* gq = g_q + head_base + (size_t)q0 * HDIM;
    const float* gk = g_k + head_base;
    const float* gv = g_v + head_base;

#pragma unroll
    for (int it = 0; it < 4; it++) {
        int e = tid + it * 256;
        int r = e >> 4;
        int c = (e & 15) << 2;
        float4 v = *(const float4*)&gq[(size_t)r * HDIM + c];
        v.x *= QSCALE; v.y *= QSCALE; v.z *= QSCALE; v.w *= QSCALE;
        *(float4*)&Qs[r * PAD + c] = v;
    }

    float m_i[4], l_i[4], acc[4][4];
#pragma unroll
    for (int i = 0; i < 4; i++) {
        m_i[i] = -INFINITY; l_i[i] = 0.f;
#pragma unroll
        for (int j = 0; j < 4; j++) acc[i][j] = 0.f;
    }
    __syncthreads();

    for (int kt = 0; kt <= qt; kt++) {
        const int k0 = kt * 64;
#pragma unroll
        for (int it = 0; it < 4; it++) {
            int e = tid + it * 256;
            int r = e >> 4;
            int c = (e & 15) << 2;
            *(float4*)&Ks[r * PAD + c] = *(const float4*)&gk[(size_t)(k0 + r) * HDIM + c];
            *(float4*)&Vs[r * PAD + c] = *(const float4*)&gv[(size_t)(k0 + r) * HDIM + c];
        }
        __syncthreads();

        float s[4][4];
#pragma unroll
        for (int i = 0; i < 4; i++)
#pragma unroll
            for (int j = 0; j < 4; j++) s[i][j] = 0.f;

#pragma unroll
        for (int k = 0; k < 64; k += 4) {
            float4 q[4], kk[4];
#pragma unroll
            for (int i = 0; i < 4; i++) q[i]  = *(float4*)&Qs[(ty * 4 + i) * PAD + k];
#pragma unroll
            for (int j = 0; j < 4; j++) kk[j] = *(float4*)&Ks[(tx * 4 + j) * PAD + k];
#pragma unroll
            for (int i = 0; i < 4; i++)
#pragma unroll
                for (int j = 0; j < 4; j++) {
                    s[i][j] = fmaf(q[i].x, kk[j].x, s[i][j]);
                    s[i][j] = fmaf(q[i].y, kk[j].y, s[i][j]);
                    s[i][j] = fmaf(q[i].z, kk[j].z, s[i][j]);
                    s[i][j] = fmaf(q[i].w, kk[j].w, s[i][j]);
                }
        }

        if (kt == qt) {
#pragma unroll
            for (int i = 0; i < 4; i++)
#pragma unroll
                for (int j = 0; j < 4; j++)
                    if (tx * 4 + j > ty * 4 + i) s[i][j] = -INFINITY;
        }

#pragma unroll
        for (int i = 0; i < 4; i++) {
            float mloc = fmaxf(fmaxf(s[i][0], s[i][1]), fmaxf(s[i][2], s[i][3]));
#pragma unroll
            for (int o = 1; o < 16; o <<= 1)
                mloc = fmaxf(mloc, __shfl_xor_sync(0xffffffffu, mloc, o));
            float mn = fmaxf(m_i[i], mloc);
            float fac = ex2f(m_i[i] - mn);
            float psum = 0.f;
#pragma unroll
            for (int j = 0; j < 4; j++) {
                float p = ex2f(s[i][j] - mn);
                s[i][j] = p;
                psum += p;
            }
#pragma unroll
            for (int o = 1; o < 16; o <<= 1)
                psum += __shfl_xor_sync(0xffffffffu, psum, o);
            l_i[i] = l_i[i] * fac + psum;
            m_i[i] = mn;
#pragma unroll
            for (int j = 0; j < 4; j++) acc[i][j] *= fac;
        }

#pragma unroll
        for (int i = 0; i < 4; i++)
#pragma unroll
            for (int j = 0; j < 4; j++)
                Ps[(ty * 4 + i) * PAD + tx * 4 + j] = s[i][j];
        __syncthreads();

#pragma unroll
        for (int k = 0; k < 64; k++) {
            float4 vv = *(float4*)&Vs[k * PAD + tx * 4];
#pragma unroll
            for (int i = 0; i < 4; i++) {
                float p = Ps[(ty * 4 + i) * PAD + k];
                acc[i][0] = fmaf(p, vv.x, acc[i][0]);
                acc[i][1] = fmaf(p, vv.y, acc[i][1]);
                acc[i][2] = fmaf(p, vv.z, acc[i][2]);
                acc[i][3] = fmaf(p, vv.w, acc[i][3]);
            }
        }
        __syncthreads();
    }

#pragma unroll
    for (int i = 0; i < 4; i++) {
        float rn = 1.0f / l_i[i];
        int t = q0 + ty * 4 + i;
        float4 v = make_float4(acc[i][0] * rn, acc[i][1] * rn,
                               acc[i][2] * rn, acc[i][3] * rn);
        *(float4*)&g_y[((size_t)b * SEQ + t) * EMBD + h * HDIM + tx * 4] = v;
    }
}

// ---------------------------------------------------------------------------
extern "C" void kernel_launch(void* const* d_in, const int* in_sizes, int n_in,
                              void* d_out, int out_size)
{
    const float* x  = (const float*)d_in[0];
    const float* Wq = (const float*)d_in[1];
    const float* Wk = (const float*)d_in[2];
    const float* Wv = (const float*)d_in[3];
    const float* Wp = (const float*)d_in[4];
    const float* bp = (const float*)d_in[5];
    float* out = (float*)d_out;

    cudaFuncSetAttribute(gemm_mma, cudaFuncAttributeMaxDynamicSharedMemorySize, GEMM_SMEM);
    const int attn_smem = 4 * 64 * PAD * sizeof(float);
    cudaFuncSetAttribute(attn_fwd, cudaFuncAttributeMaxDynamicSharedMemorySize, attn_smem);

    __nv_bfloat16 *xhi, *xlo, *yhi, *ylo, *wthi, *wtlo;
    float* yp;
    cudaGetSymbolAddress((void**)&xhi,  g_xhi);
    cudaGetSymbolAddress((void**)&xlo,  g_xlo);
    cudaGetSymbolAddress((void**)&yhi,  g_yhi);
    cudaGetSymbolAddress((void**)&ylo,  g_ylo);
    cudaGetSymbolAddress((void**)&wthi, g_wthi);
    cudaGetSymbolAddress((void**)&wtlo, g_wtlo);
    cudaGetSymbolAddress((void**)&yp,   g_y);

    // 1) split x into bf16 hi/lo
    split_kernel<<<2048, 256>>>(x, xhi, xlo, MTOT * EMBD / 4);
    // 2) transpose + split all 4 weight matrices
    wsplit_kernel<<<dim3(32, 32, 4), 256>>>(Wq, Wk, Wv, Wp);
    // 3) QKV projections on tensor pipe (mma.sync, split-bf16)
    gemm_mma<<<dim3(EMBD / BN, MTOT / BM, 3), 256, GEMM_SMEM>>>(
        xhi, xlo, wthi, wtlo, nullptr, nullptr, 0);
    // 4) attention
    attn_fwd<<<dim3(SEQ / 64, NHEAD, BATCH), 256, attn_smem>>>();
    // 5) split attention output
    split_kernel<<<2048, 256>>>(yp, yhi, ylo, MTOT * EMBD / 4);
    // 6) output projection + bias
    gemm_mma<<<dim3(EMBD / BN, MTOT / BM, 1), 256, GEMM_SMEM>>>(
        yhi, ylo, wthi + 3 * (size_t)EMBD * EMBD, wtlo + 3 * (size_t)EMBD * EMBD,
        bp, out, 1);
}

// round 4
// speedup vs baseline: 3.1990x; 2.3635x over previous
#include <cuda_runtime.h>
#include <cuda_bf16.h>
#include <cuda_fp16.h>
#include <math.h>
#include <stdint.h>

// Problem constants
#define BATCH 4
#define SEQ   2048
#define EMBD  1024
#define NHEAD 16
#define HDIM  64
#define MTOT  (BATCH*SEQ)   // 8192
#define QSCALE 0.1803368801111137f   // 0.125 * log2(e)

// ---------------------------------------------------------------------------
// Device scratch
// ---------------------------------------------------------------------------
__device__ __nv_bfloat16 g_qhi[BATCH*NHEAD*SEQ*HDIM];  // [B,H,T,d] (pre-scaled)
__device__ __nv_bfloat16 g_qlo[BATCH*NHEAD*SEQ*HDIM];
__device__ __nv_bfloat16 g_khi[BATCH*NHEAD*SEQ*HDIM];
__device__ __nv_bfloat16 g_klo[BATCH*NHEAD*SEQ*HDIM];
__device__ __half        g_vhi[BATCH*NHEAD*SEQ*HDIM];
__device__ __half        g_vlo[BATCH*NHEAD*SEQ*HDIM];
__device__ float g_y[BATCH*SEQ*EMBD];                   // attention out [B,T,C]

__device__ __nv_bfloat16 g_xhi[MTOT*EMBD];
__device__ __nv_bfloat16 g_xlo[MTOT*EMBD];
__device__ __nv_bfloat16 g_yhi[MTOT*EMBD];
__device__ __nv_bfloat16 g_ylo[MTOT*EMBD];
__device__ __nv_bfloat16 g_wthi[4*EMBD*EMBD];           // W^T hi: [z][n][k]
__device__ __nv_bfloat16 g_wtlo[4*EMBD*EMBD];

// ---------------------------------------------------------------------------
// PTX helpers (arch-generic only — harness compiles compute_103)
// ---------------------------------------------------------------------------
__device__ __forceinline__ uint32_t smem_u32(const void* p) {
    uint32_t a;
    asm("{ .reg .u64 t; cvta.to.shared.u64 t, %1; cvt.u32.u64 %0, t; }"
        : "=r"(a) : "l"(p));
    return a;
}
__device__ __forceinline__ void cp16(uint32_t dst, const void* src) {
    asm volatile("cp.async.cg.shared.global [%0], [%1], 16;"
                 :: "r"(dst), "l"(src) : "memory");
}
#define CP_COMMIT() asm volatile("cp.async.commit_group;" ::: "memory")
#define CP_WAIT(n)  asm volatile("cp.async.wait_group %0;" :: "n"(n) : "memory")

#define LDSM_X4(r0, r1, r2, r3, addr) \
    asm volatile("ldmatrix.sync.aligned.m8n8.x4.shared.b16 {%0,%1,%2,%3}, [%4];" \
        : "=r"(r0), "=r"(r1), "=r"(r2), "=r"(r3) : "r"(addr))
#define LDSM_X2(r0, r1, addr) \
    asm volatile("ldmatrix.sync.aligned.m8n8.x2.shared.b16 {%0,%1}, [%2];" \
        : "=r"(r0), "=r"(r1) : "r"(addr))
#define LDSM_X2_T(r0, r1, addr) \
    asm volatile("ldmatrix.sync.aligned.m8n8.x2.trans.shared.b16 {%0,%1}, [%2];" \
        : "=r"(r0), "=r"(r1) : "r"(addr))

#define MMA_BF16(d, a0, a1, a2, a3, b0, b1) \
    asm volatile("mma.sync.aligned.m16n8k16.row.col.f32.bf16.bf16.f32 " \
        "{%0,%1,%2,%3}, {%4,%5,%6,%7}, {%8,%9}, {%0,%1,%2,%3};" \
        : "+f"((d)[0]), "+f"((d)[1]), "+f"((d)[2]), "+f"((d)[3]) \
        : "r"(a0), "r"(a1), "r"(a2), "r"(a3), "r"(b0), "r"(b1))
#define MMA_FP16(d, a0, a1, a2, a3, b0, b1) \
    asm volatile("mma.sync.aligned.m16n8k16.row.col.f32.f16.f16.f32 " \
        "{%0,%1,%2,%3}, {%4,%5,%6,%7}, {%8,%9}, {%0,%1,%2,%3};" \
        : "+f"((d)[0]), "+f"((d)[1]), "+f"((d)[2]), "+f"((d)[3]) \
        : "r"(a0), "r"(a1), "r"(a2), "r"(a3), "r"(b0), "r"(b1))

__device__ __forceinline__ float ex2f(float x) {
    float y;
    asm("ex2.approx.f32 %0, %1;" : "=f"(y) : "f"(x));
    return y;
}
// pack two fp32 -> f16x2 reg: lo = a, hi = b
__device__ __forceinline__ uint32_t pack_h2(float a, float b) {
    uint32_t r;
    asm("cvt.rn.f16x2.f32 %0, %1, %2;" : "=r"(r) : "f"(b), "f"(a));
    return r;
}

__device__ __forceinline__ void split_bf16_val(float x, __nv_bfloat16& h, __nv_bfloat16& l) {
    h = __float2bfloat16_rn(x);
    l = __float2bfloat16_rn(x - __bfloat162float(h));
}
__device__ __forceinline__ void split_fp16_val(float x, __half& h, __half& l) {
    h = __float2half_rn(x);
    l = __float2half_rn(x - __half2float(h));
}

// ---------------------------------------------------------------------------
// Elementwise split fp32 -> bf16 hi/lo
// ---------------------------------------------------------------------------
__global__ __launch_bounds__(256) void split_kernel(
    const float* __restrict__ in,
    __nv_bfloat16* __restrict__ hi, __nv_bfloat16* __restrict__ lo, int n4)
{
    int stride = gridDim.x * blockDim.x;
    for (int i = blockIdx.x * blockDim.x + threadIdx.x; i < n4; i += stride) {
        float4 v = ((const float4*)in)[i];
        __nv_bfloat16 h0, h1, h2, h3, l0, l1, l2, l3;
        split_bf16_val(v.x, h0, l0);
        split_bf16_val(v.y, h1, l1);
        split_bf16_val(v.z, h2, l2);
        split_bf16_val(v.w, h3, l3);
        __nv_bfloat162* hp = (__nv_bfloat162*)(hi + i * 4);
        __nv_bfloat162* lp = (__nv_bfloat162*)(lo + i * 4);
        hp[0] = __nv_bfloat162{h0, h1}; hp[1] = __nv_bfloat162{h2, h3};
        lp[0] = __nv_bfloat162{l0, l1}; lp[1] = __nv_bfloat162{l2, l3};
    }
}

// ---------------------------------------------------------------------------
// Weight transpose + split: Wt[z][n][k] = split(W[k][n])
// ---------------------------------------------------------------------------
__global__ __launch_bounds__(256) void wsplit_kernel(
    const float* __restrict__ Wq, const float* __restrict__ Wk,
    const float* __restrict__ Wv, const float* __restrict__ Wp)
{
    __shared__ float ts[32][33];
    const int z = blockIdx.z;
    const float* W = (z == 0) ? Wq : (z == 1) ? Wk : (z == 2) ? Wv : Wp;
    __nv_bfloat16* oh = g_wthi + (size_t)z * EMBD * EMBD;
    __nv_bfloat16* ol = g_wtlo + (size_t)z * EMBD * EMBD;
    const int k0 = blockIdx.x * 32;
    const int n0 = blockIdx.y * 32;
    const int tx = threadIdx.x & 31;
    const int ty = threadIdx.x >> 5;
#pragma unroll
    for (int i = 0; i < 4; i++) {
        int r = ty + i * 8;
        ts[r][tx] = W[(size_t)(k0 + r) * EMBD + n0 + tx];
    }
    __syncthreads();
#pragma unroll
    for (int i = 0; i < 4; i++) {
        int r = ty + i * 8;
        float v = ts[tx][r];
        __nv_bfloat16 h, l;
        split_bf16_val(v, h, l);
        oh[(size_t)(n0 + r) * EMBD + k0 + tx] = h;
        ol[(size_t)(n0 + r) * EMBD + k0 + tx] = l;
    }
}

// ---------------------------------------------------------------------------
// bf16 mma.sync GEMM (split-bf16, 3 products): C = A @ B^T
// mode 0: out -> Q/K/V split arrays ([B,H,T,d]) by blockIdx.z
// mode 1: outp + bias (fp32)
// ---------------------------------------------------------------------------
#define BM 128
#define BN 128
#define BK 32
#define NCHUNK (EMBD / BK)
#define ROWB  80
#define SA_HI 0
#define SA_LO 10240
#define SB_HI 20480
#define SB_LO 30720
#define STG   40960
#define GEMM_SMEM (3 * STG)

__device__ __forceinline__ void load_stage(
    uint32_t stage_base,
    const __nv_bfloat16* __restrict__ Ahi, const __nv_bfloat16* __restrict__ Alo,
    const __nv_bfloat16* __restrict__ Bhi, const __nv_bfloat16* __restrict__ Blo,
    int m0, int n0, int kc, int tid)
{
#pragma unroll
    for (int i = 0; i < 2; i++) {
        int idx = tid + i * 256;
        int r  = idx >> 2;
        int ch = idx & 3;
        uint32_t d = stage_base + (uint32_t)(r * ROWB + ch * 16);
        size_t ga = (size_t)(m0 + r) * EMBD + kc + ch * 8;
        size_t gb = (size_t)(n0 + r) * EMBD + kc + ch * 8;
        cp16(d + SA_HI, Ahi + ga);
        cp16(d + SA_LO, Alo + ga);
        cp16(d + SB_HI, Bhi + gb);
        cp16(d + SB_LO, Blo + gb);
    }
    CP_COMMIT();
}

__global__ __launch_bounds__(256, 1) void gemm_mma(
    const __nv_bfloat16* __restrict__ Ahi, const __nv_bfloat16* __restrict__ Alo,
    const __nv_bfloat16* __restrict__ Bhi_all, const __nv_bfloat16* __restrict__ Blo_all,
    const float* __restrict__ bias, float* __restrict__ outp, int mode)
{
    extern __shared__ char smch[];
    const uint32_t sb = smem_u32(smch);

    const int tid  = threadIdx.x;
    const int lane = tid & 31;
    const int wid  = tid >> 5;
    const int m_w  = (wid & 1) * 64;
    const int n_w  = (wid >> 1) * 32;
    const int n0 = blockIdx.x * BN;
    const int m0 = blockIdx.y * BM;
    const int z  = blockIdx.z;
    const __nv_bfloat16* Bhi = Bhi_all + (size_t)z * EMBD * EMBD;
    const __nv_bfloat16* Blo = Blo_all + (size_t)z * EMBD * EMBD;

    float acc[4][4][4];
#pragma unroll
    for (int i = 0; i < 4; i++)
#pragma unroll
        for (int j = 0; j < 4; j++)
#pragma unroll
            for (int e = 0; e < 4; e++) acc[i][j][e] = 0.f;

    load_stage(sb + 0 * STG, Ahi, Alo, Bhi, Blo, m0, n0, 0 * BK, tid);
    load_stage(sb + 1 * STG, Ahi, Alo, Bhi, Blo, m0, n0, 1 * BK, tid);
    load_stage(sb + 2 * STG, Ahi, Alo, Bhi, Blo, m0, n0, 2 * BK, tid);

    const uint32_t a_row_off = (uint32_t)((m_w + (lane & 15)) * ROWB) + ((lane >> 4) * 16);
    const uint32_t b_row_off = (uint32_t)((n_w + (lane & 7)) * ROWB) + (((lane >> 3) & 1) * 16);

    for (int c = 0; c < NCHUNK; c++) {
        const int s = c % 3;
        if (c >= NCHUNK - 3) CP_WAIT(0); else CP_WAIT(2);
        __syncthreads();

        const uint32_t stb = sb + (uint32_t)s * STG;
#pragma unroll
        for (int ks = 0; ks < 2; ks++) {
            uint32_t ahi[4][4], alo[4][4], bhi[4][2], blo[4][2];
            const uint32_t kso = (uint32_t)(ks * 32);
#pragma unroll
            for (int i = 0; i < 4; i++) {
                uint32_t aaddr = stb + a_row_off + (uint32_t)(i * 16 * ROWB) + kso;
                LDSM_X4(ahi[i][0], ahi[i][1], ahi[i][2], ahi[i][3], aaddr + SA_HI);
                LDSM_X4(alo[i][0], alo[i][1], alo[i][2], alo[i][3], aaddr + SA_LO);
            }
#pragma unroll
            for (int j = 0; j < 4; j++) {
                uint32_t baddr = stb + b_row_off + (uint32_t)(j * 8 * ROWB) + kso;
                LDSM_X2(bhi[j][0], bhi[j][1], baddr + SB_HI);
                LDSM_X2(blo[j][0], blo[j][1], baddr + SB_LO);
            }
#pragma unroll
            for (int i = 0; i < 4; i++)
#pragma unroll
                for (int j = 0; j < 4; j++) {
                    MMA_BF16(acc[i][j], ahi[i][0], ahi[i][1], ahi[i][2], ahi[i][3],
                             bhi[j][0], bhi[j][1]);
                    MMA_BF16(acc[i][j], ahi[i][0], ahi[i][1], ahi[i][2], ahi[i][3],
                             blo[j][0], blo[j][1]);
                    MMA_BF16(acc[i][j], alo[i][0], alo[i][1], alo[i][2], alo[i][3],
                             bhi[j][0], bhi[j][1]);
                }
        }
        __syncthreads();
        if (c + 3 < NCHUNK)
            load_stage(stb, Ahi, Alo, Bhi, Blo, m0, n0, (c + 3) * BK, tid);
    }

    const int b  = m0 >> 11;
    const int rr = m0 + m_w + (lane >> 2);
#pragma unroll
    for (int i = 0; i < 4; i++) {
        const int r0 = rr + i * 16;
        const int t0 = r0 & 2047;
#pragma unroll
        for (int j = 0; j < 4; j++) {
            const int cc = n0 + n_w + j * 8 + 2 * (lane & 3);
            if (mode == 0) {
                const int h  = cc >> 6;
                const int dd = cc & 63;
                size_t i0 = (((size_t)(b * NHEAD + h) * SEQ + t0) << 6) + dd;
                size_t i1 = i0 + (8 << 6);
                float v0 = acc[i][j][0], v1 = acc[i][j][1];
                float v2 = acc[i][j][2], v3 = acc[i][j][3];
                if (z == 0) { v0 *= QSCALE; v1 *= QSCALE; v2 *= QSCALE; v3 *= QSCALE; }
                if (z == 2) {
                    __half h0, l0, h1, l1;
                    split_fp16_val(v0, h0, l0); split_fp16_val(v1, h1, l1);
                    *(__half2*)&g_vhi[i0] = __half2{h0, h1};
                    *(__half2*)&g_vlo[i0] = __half2{l0, l1};
                    split_fp16_val(v2, h0, l0); split_fp16_val(v3, h1, l1);
                    *(__half2*)&g_vhi[i1] = __half2{h0, h1};
                    *(__half2*)&g_vlo[i1] = __half2{l0, l1};
                } else {
                    __nv_bfloat16* dh = (z == 0) ? g_qhi : g_khi;
                    __nv_bfloat16* dl = (z == 0) ? g_qlo : g_klo;
                    __nv_bfloat16 h0, l0, h1, l1;
                    split_bf16_val(v0, h0, l0); split_bf16_val(v1, h1, l1);
                    *(__nv_bfloat162*)&dh[i0] = __nv_bfloat162{h0, h1};
                    *(__nv_bfloat162*)&dl[i0] = __nv_bfloat162{l0, l1};
                    split_bf16_val(v2, h0, l0); split_bf16_val(v3, h1, l1);
                    *(__nv_bfloat162*)&dh[i1] = __nv_bfloat162{h0, h1};
                    *(__nv_bfloat162*)&dl[i1] = __nv_bfloat162{l0, l1};
                }
            } else {
                float2 bv = *(const float2*)&bias[cc];
                float* p = outp + (size_t)r0 * EMBD + cc;
                *(float2*)p = make_float2(acc[i][j][0] + bv.x, acc[i][j][1] + bv.y);
                *(float2*)(p + 8 * EMBD) =
                    make_float2(acc[i][j][2] + bv.x, acc[i][j][3] + bv.y);
            }
        }
    }
}

// ---------------------------------------------------------------------------
// Tensor-core causal flash attention (FA2 style).
// Br=128 (8 warps x 16 rows), Bc=64, d=64.
// S: 3-product split-bf16 (Q,K).  P: fp16.  PV: 2-product split-fp16 V.
// ---------------------------------------------------------------------------
#define ROWP 144      // 64 elems * 2B = 128B, +16B pad
#define SQ_HI 0
#define SQ_LO 18432
#define STAGE0 36864
#define ASTG  36864   // per stage: KH,KL,VH,VL each 64*144=9216
#define OFF_KH 0
#define OFF_KL 9216
#define OFF_VH 18432
#define OFF_VL 27648
#define ATTN_SMEM (STAGE0 + 2 * ASTG)   // 110592

__global__ __launch_bounds__(256, 1) void attn_tc()
{
    extern __shared__ char smch[];
    const uint32_t sb = smem_u32(smch);

    const int tid  = threadIdx.x;
    const int lane = tid & 31;
    const int w    = tid >> 5;

    const int qt = gridDim.x - 1 - blockIdx.x;  // heavy tiles first
    const int h  = blockIdx.y;
    const int b  = blockIdx.z;
    const int q0 = qt * 128;
    const int kt_end = qt * 2 + 2;

    const size_t hb = ((size_t)(b * NHEAD + h)) * SEQ * HDIM;
    const __nv_bfloat16* qhi = g_qhi + hb + (size_t)q0 * HDIM;
    const __nv_bfloat16* qlo = g_qlo + hb + (size_t)q0 * HDIM;
    const __nv_bfloat16* khi = g_khi + hb;
    const __nv_bfloat16* klo = g_klo + hb;
    const __half*        vhi = g_vhi + hb;
    const __half*        vlo = g_vlo + hb;

    // --- issue Q loads (group 0) ---
#pragma unroll
    for (int i = 0; i < 4; i++) {
        int idx = tid + i * 256;       // 1024: 128 rows x 8 chunks
        int r = idx >> 3, ch = idx & 7;
        uint32_t d = sb + (uint32_t)(r * ROWP + ch * 16);
        cp16(d + SQ_HI, qhi + (size_t)r * HDIM + ch * 8);
        cp16(d + SQ_LO, qlo + (size_t)r * HDIM + ch * 8);
    }
    CP_COMMIT();

    // --- prologue K/V stages for kt=0,1 ---
#pragma unroll
    for (int st = 0; st < 2; st++) {
        uint32_t base = sb + STAGE0 + st * ASTG;
        int k0 = st * 64;
#pragma unroll
        for (int i = 0; i < 2; i++) {
            int idx = tid + i * 256;   // 512: 64 rows x 8 chunks
            int r = idx >> 3, ch = idx & 7;
            uint32_t d = base + (uint32_t)(r * ROWP + ch * 16);
            size_t g = (size_t)(k0 + r) * HDIM + ch * 8;
            cp16(d + OFF_KH, khi + g);
            cp16(d + OFF_KL, klo + g);
            cp16(d + OFF_VH, vhi + g);
            cp16(d + OFF_VL, vlo + g);
        }
        CP_COMMIT();
    }

    // --- Q A-frags into registers ---
    CP_WAIT(2);
    __syncthreads();
    uint32_t qh[4][4], ql[4][4];
    {
        uint32_t arow = sb + (uint32_t)((w * 16 + (lane & 15)) * ROWP) + ((lane >> 4) * 16);
#pragma unroll
        for (int t = 0; t < 4; t++) {
            LDSM_X4(qh[t][0], qh[t][1], qh[t][2], qh[t][3], arow + SQ_HI + t * 32);
            LDSM_X4(ql[t][0], ql[t][1], ql[t][2], ql[t][3], arow + SQ_LO + t * 32);
        }
    }

    float o[8][4];
#pragma unroll
    for (int j = 0; j < 8; j++)
#pragma unroll
        for (int e = 0; e < 4; e++) o[j][e] = 0.f;
    float m0s = -INFINITY, m1s = -INFINITY, l0s = 0.f, l1s = 0.f;

    const int warp_rmin = q0 + w * 16;
    const int warp_rmax = warp_rmin + 15;
    const int row0 = warp_rmin + (lane >> 2);    // rows for c0/c1
    const int row1 = row0 + 8;                   // rows for c2/c3
    const int kcol = 2 * (lane & 3);

    for (int kt = 0; kt < kt_end; kt++) {
        if (kt + 1 < kt_end) CP_WAIT(1); else CP_WAIT(0);
        __syncthreads();

        const int k0 = kt * 64;
        const uint32_t stg = sb + STAGE0 + (kt & 1) * ASTG;
        const bool active = (k0 <= warp_rmax);

        if (active) {
            // ---- S = Q K^T (3-product split bf16) ----
            float s[8][4];
#pragma unroll
            for (int j = 0; j < 8; j++)
#pragma unroll
                for (int e = 0; e < 4; e++) s[j][e] = 0.f;

            const uint32_t brow = stg + (uint32_t)((lane & 7) * ROWP) + (((lane >> 3) & 1) * 16);
#pragma unroll
            for (int j = 0; j < 8; j++) {
                uint32_t kb0[4][2], kb1[4][2];
#pragma unroll
                for (int t = 0; t < 4; t++) {
                    uint32_t ba = brow + (uint32_t)(j * 8 * ROWP) + t * 32;
                    LDSM_X2(kb0[t][0], kb0[t][1], ba + OFF_KH);
                    LDSM_X2(kb1[t][0], kb1[t][1], ba + OFF_KL);
                }
#pragma unroll
                for (int t = 0; t < 4; t++) {
                    MMA_BF16(s[j], qh[t][0], qh[t][1], qh[t][2], qh[t][3], kb0[t][0], kb0[t][1]);
                    MMA_BF16(s[j], qh[t][0], qh[t][1], qh[t][2], qh[t][3], kb1[t][0], kb1[t][1]);
                    MMA_BF16(s[j], ql[t][0], ql[t][1], ql[t][2], ql[t][3], kb0[t][0], kb0[t][1]);
                }
            }

            // ---- causal mask (only when tile straddles diagonal for this warp)
            if (k0 + 63 > warp_rmin) {
#pragma unroll
                for (int j = 0; j < 8; j++) {
                    int kg = k0 + j * 8 + kcol;
                    if (kg     > row0) s[j][0] = -1e30f;
                    if (kg + 1 > row0) s[j][1] = -1e30f;
                    if (kg     > row1) s[j][2] = -1e30f;
                    if (kg + 1 > row1) s[j][3] = -1e30f;
                }
            }

            // ---- online softmax (base-2) ----
            float mx0 = s[0][0], mx1 = s[0][2];
#pragma unroll
            for (int j = 0; j < 8; j++) {
                mx0 = fmaxf(mx0, fmaxf(s[j][0], s[j][1]));
                mx1 = fmaxf(mx1, fmaxf(s[j][2], s[j][3]));
            }
            mx0 = fmaxf(mx0, __shfl_xor_sync(0xffffffffu, mx0, 1));
            mx0 = fmaxf(mx0, __shfl_xor_sync(0xffffffffu, mx0, 2));
            mx1 = fmaxf(mx1, __shfl_xor_sync(0xffffffffu, mx1, 1));
            mx1 = fmaxf(mx1, __shfl_xor_sync(0xffffffffu, mx1, 2));
            float mn0 = fmaxf(m0s, mx0), mn1 = fmaxf(m1s, mx1);
            float f0 = ex2f(m0s - mn0), f1 = ex2f(m1s - mn1);
            float ps0 = 0.f, ps1 = 0.f;
#pragma unroll
            for (int j = 0; j < 8; j++) {
                s[j][0] = ex2f(s[j][0] - mn0);
                s[j][1] = ex2f(s[j][1] - mn0);
                s[j][2] = ex2f(s[j][2] - mn1);
                s[j][3] = ex2f(s[j][3] - mn1);
                ps0 += s[j][0] + s[j][1];
                ps1 += s[j][2] + s[j][3];
            }
            ps0 += __shfl_xor_sync(0xffffffffu, ps0, 1);
            ps0 += __shfl_xor_sync(0xffffffffu, ps0, 2);
            ps1 += __shfl_xor_sync(0xffffffffu, ps1, 1);
            ps1 += __shfl_xor_sync(0xffffffffu, ps1, 2);
            l0s = l0s * f0 + ps0;
            l1s = l1s * f1 + ps1;
            m0s = mn0; m1s = mn1;
#pragma unroll
            for (int j = 0; j < 8; j++) {
                o[j][0] *= f0; o[j][1] *= f0;
                o[j][2] *= f1; o[j][3] *= f1;
            }

            // ---- pack P to fp16 A-frags ----
            uint32_t pa[4][4];
#pragma unroll
            for (int t = 0; t < 4; t++) {
                pa[t][0] = pack_h2(s[2*t][0],   s[2*t][1]);
                pa[t][1] = pack_h2(s[2*t][2],   s[2*t][3]);
                pa[t][2] = pack_h2(s[2*t+1][0], s[2*t+1][1]);
                pa[t][3] = pack_h2(s[2*t+1][2], s[2*t+1][3]);
            }

            // ---- O += P @ V (V split fp16, ldmatrix trans) ----
            const uint32_t vrow = stg + (uint32_t)((lane & 15) * ROWP);
#pragma unroll
            for (int j2 = 0; j2 < 8; j2++) {
#pragma unroll
                for (int t = 0; t < 4; t++) {
                    uint32_t va = vrow + (uint32_t)(t * 16 * ROWP) + j2 * 16;
                    uint32_t vb0, vb1;
                    LDSM_X2_T(vb0, vb1, va + OFF_VH);
                    MMA_FP16(o[j2], pa[t][0], pa[t][1], pa[t][2], pa[t][3], vb0, vb1);
                    LDSM_X2_T(vb0, vb1, va + OFF_VL);
                    MMA_FP16(o[j2], pa[t][0], pa[t][1], pa[t][2], pa[t][3], vb0, vb1);
                }
            }
        }

        __syncthreads();
        if (kt + 2 < kt_end) {
            uint32_t base = sb + STAGE0 + (kt & 1) * ASTG;
            int kn = (kt + 2) * 64;
#pragma unroll
            for (int i = 0; i < 2; i++) {
                int idx = tid + i * 256;
                int r = idx >> 3, ch = idx & 7;
                uint32_t d = base + (uint32_t)(r * ROWP + ch * 16);
                size_t g = (size_t)(kn + r) * HDIM + ch * 8;
                cp16(d + OFF_KH, khi + g);
                cp16(d + OFF_KL, klo + g);
                cp16(d + OFF_VH, vhi + g);
                cp16(d + OFF_VL, vlo + g);
            }
            CP_COMMIT();
        }
    }

    // ---- epilogue: O / l -> g_y [B,T,C] ----
    const float rn0 = 1.0f / l0s;
    const float rn1 = 1.0f / l1s;
    const int cbase = h * HDIM + kcol;
#pragma unroll
    for (int j = 0; j < 8; j++) {
        int cc = cbase + j * 8;
        *(float2*)&g_y[((size_t)b * SEQ + row0) * EMBD + cc] =
            make_float2(o[j][0] * rn0, o[j][1] * rn0);
        *(float2*)&g_y[((size_t)b * SEQ + row1) * EMBD + cc] =
            make_float2(o[j][2] * rn1, o[j][3] * rn1);
    }
}

// ---------------------------------------------------------------------------
extern "C" void kernel_launch(void* const* d_in, const int* in_sizes, int n_in,
                              void* d_out, int out_size)
{
    const float* x  = (const float*)d_in[0];
    const float* Wq = (const float*)d_in[1];
    const float* Wk = (const float*)d_in[2];
    const float* Wv = (const float*)d_in[3];
    const float* Wp = (const float*)d_in[4];
    const float* bp = (const float*)d_in[5];
    float* out = (float*)d_out;

    cudaFuncSetAttribute(gemm_mma, cudaFuncAttributeMaxDynamicSharedMemorySize, GEMM_SMEM);
    cudaFuncSetAttribute(attn_tc,  cudaFuncAttributeMaxDynamicSharedMemorySize, ATTN_SMEM);

    __nv_bfloat16 *xhi, *xlo, *yhi, *ylo, *wthi, *wtlo;
    float* yp;
    cudaGetSymbolAddress((void**)&xhi,  g_xhi);
    cudaGetSymbolAddress((void**)&xlo,  g_xlo);
    cudaGetSymbolAddress((void**)&yhi,  g_yhi);
    cudaGetSymbolAddress((void**)&ylo,  g_ylo);
    cudaGetSymbolAddress((void**)&wthi, g_wthi);
    cudaGetSymbolAddress((void**)&wtlo, g_wtlo);
    cudaGetSymbolAddress((void**)&yp,   g_y);

    // 1) split x into bf16 hi/lo
    split_kernel<<<2048, 256>>>(x, xhi, xlo, MTOT * EMBD / 4);
    // 2) transpose + split all 4 weight matrices
    wsplit_kernel<<<dim3(32, 32, 4), 256>>>(Wq, Wk, Wv, Wp);
    // 3) QKV projections -> split Q/K (bf16), V (fp16), Q pre-scaled
    gemm_mma<<<dim3(EMBD / BN, MTOT / BM, 3), 256, GEMM_SMEM>>>(
        xhi, xlo, wthi, wtlo, nullptr, nullptr, 0);
    // 4) tensor-core flash attention
    attn_tc<<<dim3(SEQ / 128, NHEAD, BATCH), 256, ATTN_SMEM>>>();
    // 5) split attention output
    split_kernel<<<2048, 256>>>(yp, yhi, ylo, MTOT * EMBD / 4);
    // 6) output projection + bias
    gemm_mma<<<dim3(EMBD / BN, MTOT / BM, 1), 256, GEMM_SMEM>>>(
        yhi, ylo, wthi + 3 * (size_t)EMBD * EMBD, wtlo + 3 * (size_t)EMBD * EMBD,
        bp, out, 1);
}